// round 13
// baseline (speedup 1.0000x reference)
#include <cuda_runtime.h>
#include <cstring>
#include <cstddef>

#define HW      4096
#define CCH     256
#define NH      4
#define RHD     8
#define HD      64
#define TOTQKV  320
#define BATCH   2

// Scratch (allocations are forbidden; __device__ globals are the sanctioned path)
__device__ float g_qkv[BATCH * TOTQKV * HW];   // [b][o][hw]  (q:0..31, k:32..63, v:64..319)
__device__ float g_att[BATCH * CCH * HW];      // [b][h*64+d][hw]

// ---- packed fp32x2 helpers (sm_103a; 2 MACs per FMA-pipe issue) ----
__device__ __forceinline__ void fma2(float2& d, float2 a, float2 b) {
    unsigned long long ud, ua, ub;
    memcpy(&ud, &d, 8); memcpy(&ua, &a, 8); memcpy(&ub, &b, 8);
    asm("fma.rn.f32x2 %0, %1, %2, %0;" : "+l"(ud) : "l"(ua), "l"(ub));
    memcpy(&d, &ud, 8);
}
__device__ __forceinline__ void mul2(float2& d, float2 a, float2 b) {
    unsigned long long ud, ua, ub;
    memcpy(&ua, &a, 8); memcpy(&ub, &b, 8);
    asm("mul.rn.f32x2 %0, %1, %2;" : "=l"(ud) : "l"(ua), "l"(ub));
    memcpy(&d, &ud, 8);
}
__device__ __forceinline__ float ex2(float x) {
    float y; asm("ex2.approx.f32 %0, %1;" : "=f"(y) : "f"(x)); return y;
}

// =====================================================================
// K1: qkv[b][o][p] = sum_c qkv_w[o][c] * x[b][c][p] + qkv_b[o]
// tiles 64o x 64p x 64c, 256 threads, 4o x 4p per thread (f32x2 packed)
// =====================================================================
__global__ __launch_bounds__(256) void k_qkv(
    const float* __restrict__ x, const float* __restrict__ w,
    const float* __restrict__ bias)
{
    __shared__ __align__(16) float sw[64][65];
    __shared__ __align__(16) float sx[64][66];
    const int b  = blockIdx.z;
    const int o0 = blockIdx.y * 64;
    const int p0 = blockIdx.x * 64;
    const int tx = threadIdx.x & 15;   // 4 p each
    const int ty = threadIdx.x >> 4;   // 4 o each
    const float* xb = x + (size_t)b * CCH * HW;

    float2 acc[4][2];
    #pragma unroll
    for (int i = 0; i < 4; i++) { acc[i][0] = make_float2(0.f,0.f); acc[i][1] = make_float2(0.f,0.f); }

    for (int c0 = 0; c0 < CCH; c0 += 64) {
        #pragma unroll
        for (int i = 0; i < 16; i++) {
            int idx = threadIdx.x + i * 256;
            int r = idx >> 6, cc = idx & 63;
            sw[r][cc] = w[(size_t)(o0 + r) * CCH + c0 + cc];
            sx[r][cc] = xb[(size_t)(c0 + r) * HW + p0 + cc];
        }
        __syncthreads();
        #pragma unroll 8
        for (int c = 0; c < 64; c++) {
            float2 xv0 = *(const float2*)&sx[c][tx * 4];
            float2 xv1 = *(const float2*)&sx[c][tx * 4 + 2];
            #pragma unroll
            for (int i = 0; i < 4; i++) {
                float wv = sw[ty * 4 + i][c];
                float2 w2 = make_float2(wv, wv);
                fma2(acc[i][0], w2, xv0);
                fma2(acc[i][1], w2, xv1);
            }
        }
        __syncthreads();
    }
    #pragma unroll
    for (int i = 0; i < 4; i++) {
        int o = o0 + ty * 4 + i;
        float bv = bias[o];
        float* op = g_qkv + ((size_t)b * TOTQKV + o) * HW + p0 + tx * 4;
        op[0] = acc[i][0].x + bv;
        op[1] = acc[i][0].y + bv;
        op[2] = acc[i][1].x + bv;
        op[3] = acc[i][1].y + bv;
    }
}

// =====================================================================
// K2: flash attention per (b, h, 64-query tile).
// 256 threads: trow = t>>3 (2 q rows each), tcol = t&7 (8 m / 8 d cols).
// Online softmax in log2 domain; PV accumulated in packed f32x2 pairs.
// =====================================================================
#define QT 64
#define MT 64
__global__ __launch_bounds__(256) void k_attn()
{
    __shared__ __align__(16) float sq[RHD][QT];
    __shared__ __align__(16) float sk[RHD][MT];
    __shared__ __align__(16) float sv[HD][MT + 2];
    __shared__ __align__(16) float sp[QT][MT + 2];

    const int b  = blockIdx.z;
    const int h  = blockIdx.y;
    const int n0 = blockIdx.x * QT;
    const float* qg = g_qkv + ((size_t)b * TOTQKV + h * RHD) * HW;
    const float* kg = g_qkv + ((size_t)b * TOTQKV + NH * RHD + h * RHD) * HW;
    const float* vg = g_qkv + ((size_t)b * TOTQKV + 2 * NH * RHD + h * HD) * HW;

    const int t    = threadIdx.x;
    const int trow = t >> 3;   // 0..31
    const int tcol = t & 7;    // 0..7

    // fold 1/sqrt(8) and log2(e) into q so softmax is a single ex2
    const float SC = 0.35355339059327373f * 1.4426950408889634f;

    for (int i = t; i < RHD * QT; i += 256)
        sq[i >> 6][i & 63] = qg[(size_t)(i >> 6) * HW + n0 + (i & 63)] * SC;

    float2 acc[2][8];
    #pragma unroll
    for (int i = 0; i < 2; i++)
        #pragma unroll
        for (int j = 0; j < 8; j++) acc[i][j] = make_float2(0.f, 0.f);
    float mrun[2] = { -1e30f, -1e30f };
    float lrun[2] = { 0.f, 0.f };

    __syncthreads();

    for (int m0 = 0; m0 < HW; m0 += MT) {
        // load K tile [8][64] and V tile [64][64]
        for (int i = t; i < RHD * MT; i += 256)
            sk[i >> 6][i & 63] = kg[(size_t)(i >> 6) * HW + m0 + (i & 63)];
        #pragma unroll
        for (int i = 0; i < 16; i++) {
            int idx = t + i * 256;
            int d = idx >> 6, mm = idx & 63;
            sv[d][mm] = vg[(size_t)d * HW + m0 + mm];
        }
        __syncthreads();

        // QK^T: s[2 q][8 m] as packed pairs
        float2 s2[2][4];
        #pragma unroll
        for (int i = 0; i < 2; i++)
            #pragma unroll
            for (int j = 0; j < 4; j++) s2[i][j] = make_float2(0.f, 0.f);
        #pragma unroll
        for (int r = 0; r < RHD; r++) {
            float2 q2[2];
            #pragma unroll
            for (int i = 0; i < 2; i++) {
                float qv = sq[r][trow * 2 + i];
                q2[i] = make_float2(qv, qv);
            }
            #pragma unroll
            for (int j = 0; j < 4; j++) {
                float2 k2 = *(const float2*)&sk[r][tcol * 8 + j * 2];
                fma2(s2[0][j], q2[0], k2);
                fma2(s2[1][j], q2[1], k2);
            }
        }

        // online softmax (row reduce over the 8 lanes sharing a q row)
        #pragma unroll
        for (int i = 0; i < 2; i++) {
            float tm = fmaxf(fmaxf(fmaxf(s2[i][0].x, s2[i][0].y), fmaxf(s2[i][1].x, s2[i][1].y)),
                             fmaxf(fmaxf(s2[i][2].x, s2[i][2].y), fmaxf(s2[i][3].x, s2[i][3].y)));
            tm = fmaxf(tm, __shfl_xor_sync(0xffffffffu, tm, 1));
            tm = fmaxf(tm, __shfl_xor_sync(0xffffffffu, tm, 2));
            tm = fmaxf(tm, __shfl_xor_sync(0xffffffffu, tm, 4));
            float nm    = fmaxf(mrun[i], tm);
            float alpha = ex2(mrun[i] - nm);
            mrun[i] = nm;
            float ps = 0.f;
            #pragma unroll
            for (int j = 0; j < 4; j++) {
                float p0 = ex2(s2[i][j].x - nm);
                float p1 = ex2(s2[i][j].y - nm);
                ps += p0 + p1;
                sp[trow * 2 + i][tcol * 8 + j * 2]     = p0;
                sp[trow * 2 + i][tcol * 8 + j * 2 + 1] = p1;
            }
            ps += __shfl_xor_sync(0xffffffffu, ps, 1);
            ps += __shfl_xor_sync(0xffffffffu, ps, 2);
            ps += __shfl_xor_sync(0xffffffffu, ps, 4);
            lrun[i] = lrun[i] * alpha + ps;
            float2 a2 = make_float2(alpha, alpha);
            #pragma unroll
            for (int j = 0; j < 8; j++) mul2(acc[i][j], acc[i][j], a2);
        }
        __syncwarp();   // sp producers/consumers share the warp

        // PV: acc[2 q][8 d] += P[q][m] * V[d][m], m packed in pairs
        const float* spr0 = sp[trow * 2];
        const float* spr1 = sp[trow * 2 + 1];
        #pragma unroll 8
        for (int m = 0; m < MT; m += 2) {
            float2 p0 = *(const float2*)(spr0 + m);
            float2 p1 = *(const float2*)(spr1 + m);
            #pragma unroll
            for (int j = 0; j < 8; j++) {
                float2 v2 = *(const float2*)&sv[tcol * 8 + j][m];
                fma2(acc[0][j], p0, v2);
                fma2(acc[1][j], p1, v2);
            }
        }
        __syncthreads();
    }

    #pragma unroll
    for (int i = 0; i < 2; i++) {
        float inv = 1.f / lrun[i];
        int n = n0 + trow * 2 + i;
        #pragma unroll
        for (int j = 0; j < 8; j++) {
            int d = tcol * 8 + j;
            g_att[((size_t)b * CCH + h * HD + d) * HW + n] = (acc[i][j].x + acc[i][j].y) * inv;
        }
    }
}

// =====================================================================
// K3: out[b][o][p] = gamma * (sum_c out_w[o][c]*att[b][c][p] + out_b[o]) + x[b][o][p]
// =====================================================================
__global__ __launch_bounds__(256) void k_proj(
    const float* __restrict__ x, const float* __restrict__ w,
    const float* __restrict__ bias, const float* __restrict__ gamma,
    float* __restrict__ out)
{
    __shared__ __align__(16) float sw[64][65];
    __shared__ __align__(16) float sx[64][66];
    const int b  = blockIdx.z;
    const int o0 = blockIdx.y * 64;
    const int p0 = blockIdx.x * 64;
    const int tx = threadIdx.x & 15;
    const int ty = threadIdx.x >> 4;
    const float* ab = g_att + (size_t)b * CCH * HW;

    float2 acc[4][2];
    #pragma unroll
    for (int i = 0; i < 4; i++) { acc[i][0] = make_float2(0.f,0.f); acc[i][1] = make_float2(0.f,0.f); }

    for (int c0 = 0; c0 < CCH; c0 += 64) {
        #pragma unroll
        for (int i = 0; i < 16; i++) {
            int idx = threadIdx.x + i * 256;
            int r = idx >> 6, cc = idx & 63;
            sw[r][cc] = w[(size_t)(o0 + r) * CCH + c0 + cc];
            sx[r][cc] = ab[(size_t)(c0 + r) * HW + p0 + cc];
        }
        __syncthreads();
        #pragma unroll 8
        for (int c = 0; c < 64; c++) {
            float2 xv0 = *(const float2*)&sx[c][tx * 4];
            float2 xv1 = *(const float2*)&sx[c][tx * 4 + 2];
            #pragma unroll
            for (int i = 0; i < 4; i++) {
                float wv = sw[ty * 4 + i][c];
                float2 w2 = make_float2(wv, wv);
                fma2(acc[i][0], w2, xv0);
                fma2(acc[i][1], w2, xv1);
            }
        }
        __syncthreads();
    }

    const float g = gamma[0];
    #pragma unroll
    for (int i = 0; i < 4; i++) {
        int o = o0 + ty * 4 + i;
        float bv = bias[o];
        size_t base = ((size_t)b * CCH + o) * HW + p0 + tx * 4;
        out[base + 0] = g * (acc[i][0].x + bv) + x[base + 0];
        out[base + 1] = g * (acc[i][0].y + bv) + x[base + 1];
        out[base + 2] = g * (acc[i][1].x + bv) + x[base + 2];
        out[base + 3] = g * (acc[i][1].y + bv) + x[base + 3];
    }
}

extern "C" void kernel_launch(void* const* d_in, const int* in_sizes, int n_in,
                              void* d_out, int out_size) {
    const float* x     = (const float*)d_in[0];
    const float* qkv_w = (const float*)d_in[1];
    const float* qkv_b = (const float*)d_in[2];
    const float* out_w = (const float*)d_in[3];
    const float* out_b = (const float*)d_in[4];
    const float* gamma = (const float*)d_in[5];
    float* out = (float*)d_out;

    k_qkv <<<dim3(HW / 64, TOTQKV / 64, BATCH), 256>>>(x, qkv_w, qkv_b);
    k_attn<<<dim3(HW / QT, NH,          BATCH), 256>>>();
    k_proj<<<dim3(HW / 64, CCH / 64,    BATCH), 256>>>(x, out_w, out_b, gamma, out);
}

// round 14
// speedup vs baseline: 1.0001x; 1.0001x over previous
#include <cuda_runtime.h>
#include <cstring>
#include <cstddef>

#define HW      4096
#define CCH     256
#define NH      4
#define RHD     8
#define HD      64
#define TOTQKV  320
#define BATCH   2

// Scratch (allocations are forbidden; __device__ globals are the sanctioned path)
__device__ float g_qkv[BATCH * TOTQKV * HW];   // [b][o][hw]  (q:0..31, k:32..63, v:64..319)
__device__ float g_att[BATCH * CCH * HW];      // [b][h*64+d][hw]

// ---- packed fp32x2 helpers (sm_103a; 2 MACs per FMA-pipe issue) ----
__device__ __forceinline__ void fma2(float2& d, float2 a, float2 b) {
    unsigned long long ud, ua, ub;
    memcpy(&ud, &d, 8); memcpy(&ua, &a, 8); memcpy(&ub, &b, 8);
    asm("fma.rn.f32x2 %0, %1, %2, %0;" : "+l"(ud) : "l"(ua), "l"(ub));
    memcpy(&d, &ud, 8);
}
__device__ __forceinline__ void mul2(float2& d, float2 a, float2 b) {
    unsigned long long ud, ua, ub;
    memcpy(&ua, &a, 8); memcpy(&ub, &b, 8);
    asm("mul.rn.f32x2 %0, %1, %2;" : "=l"(ud) : "l"(ua), "l"(ub));
    memcpy(&d, &ud, 8);
}
__device__ __forceinline__ float ex2(float x) {
    float y; asm("ex2.approx.f32 %0, %1;" : "=f"(y) : "f"(x)); return y;
}

// =====================================================================
// K1: qkv[b][o][p] = sum_c qkv_w[o][c] * x[b][c][p] + qkv_b[o]
// tiles 64o x 64p x 64c, 256 threads, 4o x 4p per thread (f32x2 packed)
// =====================================================================
__global__ __launch_bounds__(256) void k_qkv(
    const float* __restrict__ x, const float* __restrict__ w,
    const float* __restrict__ bias)
{
    __shared__ __align__(16) float sw[64][65];
    __shared__ __align__(16) float sx[64][66];
    const int b  = blockIdx.z;
    const int o0 = blockIdx.y * 64;
    const int p0 = blockIdx.x * 64;
    const int tx = threadIdx.x & 15;   // 4 p each
    const int ty = threadIdx.x >> 4;   // 4 o each
    const float* xb = x + (size_t)b * CCH * HW;

    float2 acc[4][2];
    #pragma unroll
    for (int i = 0; i < 4; i++) { acc[i][0] = make_float2(0.f,0.f); acc[i][1] = make_float2(0.f,0.f); }

    for (int c0 = 0; c0 < CCH; c0 += 64) {
        #pragma unroll
        for (int i = 0; i < 16; i++) {
            int idx = threadIdx.x + i * 256;
            int r = idx >> 6, cc = idx & 63;
            sw[r][cc] = w[(size_t)(o0 + r) * CCH + c0 + cc];
            sx[r][cc] = xb[(size_t)(c0 + r) * HW + p0 + cc];
        }
        __syncthreads();
        #pragma unroll 8
        for (int c = 0; c < 64; c++) {
            float2 xv0 = *(const float2*)&sx[c][tx * 4];
            float2 xv1 = *(const float2*)&sx[c][tx * 4 + 2];
            #pragma unroll
            for (int i = 0; i < 4; i++) {
                float wv = sw[ty * 4 + i][c];
                float2 w2 = make_float2(wv, wv);
                fma2(acc[i][0], w2, xv0);
                fma2(acc[i][1], w2, xv1);
            }
        }
        __syncthreads();
    }
    #pragma unroll
    for (int i = 0; i < 4; i++) {
        int o = o0 + ty * 4 + i;
        float bv = bias[o];
        float* op = g_qkv + ((size_t)b * TOTQKV + o) * HW + p0 + tx * 4;
        op[0] = acc[i][0].x + bv;
        op[1] = acc[i][0].y + bv;
        op[2] = acc[i][1].x + bv;
        op[3] = acc[i][1].y + bv;
    }
}

// =====================================================================
// K2: flash attention per (b, h, 64-query tile).
// 256 threads: trow = t>>3 (2 q rows each), tcol = t&7 (8 m / 8 d cols).
// Online softmax in log2 domain; PV accumulated in packed f32x2 pairs.
// =====================================================================
#define QT 64
#define MT 64
__global__ __launch_bounds__(256) void k_attn()
{
    __shared__ __align__(16) float sq[RHD][QT];
    __shared__ __align__(16) float sk[RHD][MT];
    __shared__ __align__(16) float sv[HD][MT + 2];
    __shared__ __align__(16) float sp[QT][MT + 2];

    const int b  = blockIdx.z;
    const int h  = blockIdx.y;
    const int n0 = blockIdx.x * QT;
    const float* qg = g_qkv + ((size_t)b * TOTQKV + h * RHD) * HW;
    const float* kg = g_qkv + ((size_t)b * TOTQKV + NH * RHD + h * RHD) * HW;
    const float* vg = g_qkv + ((size_t)b * TOTQKV + 2 * NH * RHD + h * HD) * HW;

    const int t    = threadIdx.x;
    const int trow = t >> 3;   // 0..31
    const int tcol = t & 7;    // 0..7

    // fold 1/sqrt(8) and log2(e) into q so softmax is a single ex2
    const float SC = 0.35355339059327373f * 1.4426950408889634f;

    for (int i = t; i < RHD * QT; i += 256)
        sq[i >> 6][i & 63] = qg[(size_t)(i >> 6) * HW + n0 + (i & 63)] * SC;

    float2 acc[2][8];
    #pragma unroll
    for (int i = 0; i < 2; i++)
        #pragma unroll
        for (int j = 0; j < 8; j++) acc[i][j] = make_float2(0.f, 0.f);
    float mrun[2] = { -1e30f, -1e30f };
    float lrun[2] = { 0.f, 0.f };

    __syncthreads();

    for (int m0 = 0; m0 < HW; m0 += MT) {
        // load K tile [8][64] and V tile [64][64]
        for (int i = t; i < RHD * MT; i += 256)
            sk[i >> 6][i & 63] = kg[(size_t)(i >> 6) * HW + m0 + (i & 63)];
        #pragma unroll
        for (int i = 0; i < 16; i++) {
            int idx = t + i * 256;
            int d = idx >> 6, mm = idx & 63;
            sv[d][mm] = vg[(size_t)d * HW + m0 + mm];
        }
        __syncthreads();

        // QK^T: s[2 q][8 m] as packed pairs
        float2 s2[2][4];
        #pragma unroll
        for (int i = 0; i < 2; i++)
            #pragma unroll
            for (int j = 0; j < 4; j++) s2[i][j] = make_float2(0.f, 0.f);
        #pragma unroll
        for (int r = 0; r < RHD; r++) {
            float2 q2[2];
            #pragma unroll
            for (int i = 0; i < 2; i++) {
                float qv = sq[r][trow * 2 + i];
                q2[i] = make_float2(qv, qv);
            }
            #pragma unroll
            for (int j = 0; j < 4; j++) {
                float2 k2 = *(const float2*)&sk[r][tcol * 8 + j * 2];
                fma2(s2[0][j], q2[0], k2);
                fma2(s2[1][j], q2[1], k2);
            }
        }

        // online softmax (row reduce over the 8 lanes sharing a q row)
        #pragma unroll
        for (int i = 0; i < 2; i++) {
            float tm = fmaxf(fmaxf(fmaxf(s2[i][0].x, s2[i][0].y), fmaxf(s2[i][1].x, s2[i][1].y)),
                             fmaxf(fmaxf(s2[i][2].x, s2[i][2].y), fmaxf(s2[i][3].x, s2[i][3].y)));
            tm = fmaxf(tm, __shfl_xor_sync(0xffffffffu, tm, 1));
            tm = fmaxf(tm, __shfl_xor_sync(0xffffffffu, tm, 2));
            tm = fmaxf(tm, __shfl_xor_sync(0xffffffffu, tm, 4));
            float nm    = fmaxf(mrun[i], tm);
            float alpha = ex2(mrun[i] - nm);
            mrun[i] = nm;
            float ps = 0.f;
            #pragma unroll
            for (int j = 0; j < 4; j++) {
                float p0 = ex2(s2[i][j].x - nm);
                float p1 = ex2(s2[i][j].y - nm);
                ps += p0 + p1;
                sp[trow * 2 + i][tcol * 8 + j * 2]     = p0;
                sp[trow * 2 + i][tcol * 8 + j * 2 + 1] = p1;
            }
            ps += __shfl_xor_sync(0xffffffffu, ps, 1);
            ps += __shfl_xor_sync(0xffffffffu, ps, 2);
            ps += __shfl_xor_sync(0xffffffffu, ps, 4);
            lrun[i] = lrun[i] * alpha + ps;
            float2 a2 = make_float2(alpha, alpha);
            #pragma unroll
            for (int j = 0; j < 8; j++) mul2(acc[i][j], acc[i][j], a2);
        }
        __syncwarp();   // sp producers/consumers share the warp

        // PV: acc[2 q][8 d] += P[q][m] * V[d][m], m packed in pairs
        const float* spr0 = sp[trow * 2];
        const float* spr1 = sp[trow * 2 + 1];
        #pragma unroll 8
        for (int m = 0; m < MT; m += 2) {
            float2 p0 = *(const float2*)(spr0 + m);
            float2 p1 = *(const float2*)(spr1 + m);
            #pragma unroll
            for (int j = 0; j < 8; j++) {
                float2 v2 = *(const float2*)&sv[tcol * 8 + j][m];
                fma2(acc[0][j], p0, v2);
                fma2(acc[1][j], p1, v2);
            }
        }
        __syncthreads();
    }

    #pragma unroll
    for (int i = 0; i < 2; i++) {
        float inv = 1.f / lrun[i];
        int n = n0 + trow * 2 + i;
        #pragma unroll
        for (int j = 0; j < 8; j++) {
            int d = tcol * 8 + j;
            g_att[((size_t)b * CCH + h * HD + d) * HW + n] = (acc[i][j].x + acc[i][j].y) * inv;
        }
    }
}

// =====================================================================
// K3: out[b][o][p] = gamma * (sum_c out_w[o][c]*att[b][c][p] + out_b[o]) + x[b][o][p]
// =====================================================================
__global__ __launch_bounds__(256) void k_proj(
    const float* __restrict__ x, const float* __restrict__ w,
    const float* __restrict__ bias, const float* __restrict__ gamma,
    float* __restrict__ out)
{
    __shared__ __align__(16) float sw[64][65];
    __shared__ __align__(16) float sx[64][66];
    const int b  = blockIdx.z;
    const int o0 = blockIdx.y * 64;
    const int p0 = blockIdx.x * 64;
    const int tx = threadIdx.x & 15;
    const int ty = threadIdx.x >> 4;
    const float* ab = g_att + (size_t)b * CCH * HW;

    float2 acc[4][2];
    #pragma unroll
    for (int i = 0; i < 4; i++) { acc[i][0] = make_float2(0.f,0.f); acc[i][1] = make_float2(0.f,0.f); }

    for (int c0 = 0; c0 < CCH; c0 += 64) {
        #pragma unroll
        for (int i = 0; i < 16; i++) {
            int idx = threadIdx.x + i * 256;
            int r = idx >> 6, cc = idx & 63;
            sw[r][cc] = w[(size_t)(o0 + r) * CCH + c0 + cc];
            sx[r][cc] = ab[(size_t)(c0 + r) * HW + p0 + cc];
        }
        __syncthreads();
        #pragma unroll 8
        for (int c = 0; c < 64; c++) {
            float2 xv0 = *(const float2*)&sx[c][tx * 4];
            float2 xv1 = *(const float2*)&sx[c][tx * 4 + 2];
            #pragma unroll
            for (int i = 0; i < 4; i++) {
                float wv = sw[ty * 4 + i][c];
                float2 w2 = make_float2(wv, wv);
                fma2(acc[i][0], w2, xv0);
                fma2(acc[i][1], w2, xv1);
            }
        }
        __syncthreads();
    }

    const float g = gamma[0];
    #pragma unroll
    for (int i = 0; i < 4; i++) {
        int o = o0 + ty * 4 + i;
        float bv = bias[o];
        size_t base = ((size_t)b * CCH + o) * HW + p0 + tx * 4;
        out[base + 0] = g * (acc[i][0].x + bv) + x[base + 0];
        out[base + 1] = g * (acc[i][0].y + bv) + x[base + 1];
        out[base + 2] = g * (acc[i][1].x + bv) + x[base + 2];
        out[base + 3] = g * (acc[i][1].y + bv) + x[base + 3];
    }
}

extern "C" void kernel_launch(void* const* d_in, const int* in_sizes, int n_in,
                              void* d_out, int out_size) {
    const float* x     = (const float*)d_in[0];
    const float* qkv_w = (const float*)d_in[1];
    const float* qkv_b = (const float*)d_in[2];
    const float* out_w = (const float*)d_in[3];
    const float* out_b = (const float*)d_in[4];
    const float* gamma = (const float*)d_in[5];
    float* out = (float*)d_out;

    k_qkv <<<dim3(HW / 64, TOTQKV / 64, BATCH), 256>>>(x, qkv_w, qkv_b);
    k_attn<<<dim3(HW / QT, NH,          BATCH), 256>>>();
    k_proj<<<dim3(HW / 64, CCH / 64,    BATCH), 256>>>(x, out_w, out_b, gamma, out);
}